// round 16
// baseline (speedup 1.0000x reference)
#include <cuda_runtime.h>

#define M_SLOTS   16
#define KEY_DIM   1024
#define TPB       256
#define PF_TILES  190        // prefetched wsum tiles (24 MB of V0)
#define TILE_F4   512        // f4 per wsum tile (matches wsum blocking)

// softmax weights, produced by weights_kernel, consumed by wsum_kernel
__device__ float g_w[M_SLOTS];

// ---------------------------------------------------------------------------
// Kernel 1 (PDL primary), grid = 1 + PF_TILES blocks:
//   block 0      : cosine similarity + softmax (8 warps x 2 slots).
//   blocks 1..N  : prefetch wsum's wave-1 working set (tiles 0..N-1, all 16
//                  slots) into L2 with volatile discard-loads — converts this
//                  node's duration into useful DRAM streaming.
// ---------------------------------------------------------------------------
__global__ void __launch_bounds__(TPB) weights_kernel(
        const float* __restrict__ task_emb,
        const float* __restrict__ K_memory,
        const float4* __restrict__ V0,
        int nv4_0) {
#if __CUDA_ARCH__ >= 900
    cudaTriggerProgrammaticLaunchCompletion();
#endif
    const int tid = threadIdx.x;

    if (blockIdx.x != 0) {
        // ---- prefetch tile (blockIdx.x - 1): 16 slots x 512 f4 ----
        const int t = (int)blockIdx.x - 1;
        const size_t base = (size_t)t * TILE_F4 + tid;
        #pragma unroll
        for (int m = 0; m < M_SLOTS; m++) {
            const float4* p = V0 + (size_t)m * (size_t)nv4_0 + base;
            float4 a, b;
            asm volatile("ld.global.nc.v4.f32 {%0, %1, %2, %3}, [%4];"
                         : "=f"(a.x), "=f"(a.y), "=f"(a.z), "=f"(a.w) : "l"(p));
            asm volatile("ld.global.nc.v4.f32 {%0, %1, %2, %3}, [%4];"
                         : "=f"(b.x), "=f"(b.y), "=f"(b.z), "=f"(b.w) : "l"(p + TPB));
            // results intentionally unused; volatile prevents elision
        }
        return;
    }

    // ---- block 0: weights (8 warps, 2 slots per warp) ----
    __shared__ float s_cos[M_SLOTS];
    const int warp = tid >> 5;
    const int lane = tid & 31;
    const int sa = 2 * warp, sb = 2 * warp + 1;

    const float4* t4 = (const float4*)task_emb;
    const float4* ka = (const float4*)(K_memory + sa * KEY_DIM);
    const float4* kb = (const float4*)(K_memory + sb * KEY_DIM);

    float dota = 0.f, dotb = 0.f, kka = 0.f, kkb = 0.f, tt = 0.f;
    #pragma unroll
    for (int j = 0; j < 8; j++) {
        float4 t = t4[lane + 32 * j];
        float4 a = ka[lane + 32 * j];
        float4 b = kb[lane + 32 * j];
        dota = fmaf(t.x, a.x, dota); dota = fmaf(t.y, a.y, dota);
        dota = fmaf(t.z, a.z, dota); dota = fmaf(t.w, a.w, dota);
        dotb = fmaf(t.x, b.x, dotb); dotb = fmaf(t.y, b.y, dotb);
        dotb = fmaf(t.z, b.z, dotb); dotb = fmaf(t.w, b.w, dotb);
        kka  = fmaf(a.x, a.x, kka);  kka  = fmaf(a.y, a.y, kka);
        kka  = fmaf(a.z, a.z, kka);  kka  = fmaf(a.w, a.w, kka);
        kkb  = fmaf(b.x, b.x, kkb);  kkb  = fmaf(b.y, b.y, kkb);
        kkb  = fmaf(b.z, b.z, kkb);  kkb  = fmaf(b.w, b.w, kkb);
        tt   = fmaf(t.x, t.x, tt);   tt   = fmaf(t.y, t.y, tt);
        tt   = fmaf(t.z, t.z, tt);   tt   = fmaf(t.w, t.w, tt);
    }
    #pragma unroll
    for (int off = 16; off > 0; off >>= 1) {
        dota += __shfl_down_sync(0xffffffffu, dota, off);
        dotb += __shfl_down_sync(0xffffffffu, dotb, off);
        kka  += __shfl_down_sync(0xffffffffu, kka,  off);
        kkb  += __shfl_down_sync(0xffffffffu, kkb,  off);
        tt   += __shfl_down_sync(0xffffffffu, tt,   off);
    }
    if (lane == 0) {
        float n1 = sqrtf(tt);
        s_cos[sa] = dota / fmaxf(n1 * sqrtf(kka), 1e-6f);
        s_cos[sb] = dotb / fmaxf(n1 * sqrtf(kkb), 1e-6f);
    }
    __syncthreads();

    if (tid == 0) {
        float mx = -1e30f;
        #pragma unroll
        for (int m = 0; m < M_SLOTS; m++) mx = fmaxf(mx, s_cos[m]);
        float e[M_SLOTS];
        float sum = 0.f;
        #pragma unroll
        for (int m = 0; m < M_SLOTS; m++) { e[m] = __expf(s_cos[m] - mx); sum += e[m]; }
        float inv = 1.0f / sum;
        #pragma unroll
        for (int m = 0; m < M_SLOTS; m++) g_w[m] = e[m] * inv;
    }
}

// ---------------------------------------------------------------------------
// Kernel 2 (PDL secondary): streaming weighted sum — UNCHANGED proven body
// (53.06us / 82.6% DRAM): 2 float4 per thread, evict-first hints.
// ---------------------------------------------------------------------------
__global__ void __launch_bounds__(TPB) wsum_kernel(
        const float4* __restrict__ V0,
        const float4* __restrict__ V1,
        float4* __restrict__ out,
        int nv4_0, int nv4_1) {
    const int tid   = threadIdx.x;
    const int tile0 = blockIdx.x * (TPB * 2);     // 512 f4 per block, exact fit

    const float4* __restrict__ V;
    size_t stride;
    int base;
    if (tile0 < nv4_0) { V = V0; base = tile0;          stride = (size_t)nv4_0; }
    else               { V = V1; base = tile0 - nv4_0;  stride = (size_t)nv4_1; }

#if __CUDA_ARCH__ >= 900
    cudaGridDependencySynchronize();
#endif

    float w[M_SLOTS];
    #pragma unroll
    for (int m = 0; m < M_SLOTS; m++) w[m] = g_w[m];

    float4 acc0 = make_float4(0.f, 0.f, 0.f, 0.f);
    float4 acc1 = acc0;

    #pragma unroll
    for (int m = 0; m < M_SLOTS; m++) {
        const float4* p = V + (size_t)m * stride + (size_t)base + tid;
        float4 a, b;
        asm volatile("ld.global.cs.v4.f32 {%0, %1, %2, %3}, [%4];"
                     : "=f"(a.x), "=f"(a.y), "=f"(a.z), "=f"(a.w) : "l"(p));
        asm volatile("ld.global.cs.v4.f32 {%0, %1, %2, %3}, [%4];"
                     : "=f"(b.x), "=f"(b.y), "=f"(b.z), "=f"(b.w) : "l"(p + TPB));
        float wm = w[m];
        acc0.x = fmaf(wm, a.x, acc0.x); acc0.y = fmaf(wm, a.y, acc0.y);
        acc0.z = fmaf(wm, a.z, acc0.z); acc0.w = fmaf(wm, a.w, acc0.w);
        acc1.x = fmaf(wm, b.x, acc1.x); acc1.y = fmaf(wm, b.y, acc1.y);
        acc1.z = fmaf(wm, b.z, acc1.z); acc1.w = fmaf(wm, b.w, acc1.w);
    }

    float4* dst = out + tile0 + tid;
    asm volatile("st.global.cs.v4.f32 [%0], {%1, %2, %3, %4};"
                 :: "l"(dst), "f"(acc0.x), "f"(acc0.y), "f"(acc0.z), "f"(acc0.w)
                 : "memory");
    asm volatile("st.global.cs.v4.f32 [%0], {%1, %2, %3, %4};"
                 :: "l"(dst + TPB), "f"(acc1.x), "f"(acc1.y), "f"(acc1.z), "f"(acc1.w)
                 : "memory");
}

// ---------------------------------------------------------------------------
// Launch contract
// Inputs (metadata order): task_emb [1,1024] f32, K_memory [16,1024] f32,
//                          V0 [16,1024,1024] f32, V1 [16,1024,4096] f32
// Output: rec0 [1024,1024] f32 followed by rec1 [1024,4096] f32
// ---------------------------------------------------------------------------
extern "C" void kernel_launch(void* const* d_in, const int* in_sizes, int n_in,
                              void* d_out, int out_size) {
    const float* task_emb = (const float*)d_in[0];
    const float* K_memory = (const float*)d_in[1];
    const float* V0       = (const float*)d_in[2];
    const float* V1       = (const float*)d_in[3];
    float* out = (float*)d_out;

    const int n0 = in_sizes[2] / M_SLOTS;   // 1024*1024
    const int n1 = in_sizes[3] / M_SLOTS;   // 1024*4096
    const int nv4_0 = n0 / 4;               // 262144 (= 512 tiles of 512 f4)
    const int nv4_1 = n1 / 4;               // 1048576
    const int total = nv4_0 + nv4_1;        // 1310720 = 2560 * 512 exactly

    weights_kernel<<<1 + PF_TILES, TPB>>>(task_emb, K_memory,
                                          (const float4*)V0, nv4_0);

    // Secondary with programmatic stream serialization (reproducibly +0.5us).
    cudaLaunchConfig_t cfg = {};
    cfg.gridDim  = dim3((unsigned)(total / (TPB * 2)));   // 2560
    cfg.blockDim = dim3(TPB);
    cfg.dynamicSmemBytes = 0;
    cfg.stream = 0;

    cudaLaunchAttribute attrs[1];
    attrs[0].id = cudaLaunchAttributeProgrammaticStreamSerialization;
    attrs[0].val.programmaticStreamSerializationAllowed = 1;
    cfg.attrs = attrs;
    cfg.numAttrs = 1;

    cudaLaunchKernelEx(&cfg, wsum_kernel,
                       (const float4*)V0, (const float4*)V1,
                       (float4*)out, nv4_0, nv4_1);
}

// round 17
// speedup vs baseline: 1.0044x; 1.0044x over previous
#include <cuda_runtime.h>

#define M_SLOTS 16
#define KEY_DIM 1024
#define TPB     256
#define ITEMS   4                    // float4 per thread
#define TILE_F4 (TPB * ITEMS)        // 1024 f4 per block

// softmax weights, produced by weights_kernel, consumed by wsum_kernel
__device__ float g_w[M_SLOTS];

// ---------------------------------------------------------------------------
// Kernel 1 (PDL primary): cosine similarity + softmax over 16 memory slots.
// (R15-proven version, unchanged.)
// ---------------------------------------------------------------------------
__global__ void __launch_bounds__(512) weights_kernel(
        const float* __restrict__ task_emb,
        const float* __restrict__ K_memory) {
#if __CUDA_ARCH__ >= 900
    cudaTriggerProgrammaticLaunchCompletion();
#endif
    __shared__ float s_cos[M_SLOTS];
    const int warp = threadIdx.x >> 5;
    const int lane = threadIdx.x & 31;

    const float4* t4 = (const float4*)task_emb;                 // 256 float4
    const float4* k4 = (const float4*)(K_memory + warp * KEY_DIM);

    float dot = 0.f, kk = 0.f, tt = 0.f;
    #pragma unroll
    for (int j = 0; j < 8; j++) {
        float4 t  = t4[lane + 32 * j];
        float4 km = k4[lane + 32 * j];
        dot = fmaf(t.x, km.x, dot); dot = fmaf(t.y, km.y, dot);
        dot = fmaf(t.z, km.z, dot); dot = fmaf(t.w, km.w, dot);
        kk  = fmaf(km.x, km.x, kk); kk  = fmaf(km.y, km.y, kk);
        kk  = fmaf(km.z, km.z, kk); kk  = fmaf(km.w, km.w, kk);
        tt  = fmaf(t.x,  t.x,  tt); tt  = fmaf(t.y,  t.y,  tt);
        tt  = fmaf(t.z,  t.z,  tt); tt  = fmaf(t.w,  t.w,  tt);
    }
    #pragma unroll
    for (int off = 16; off > 0; off >>= 1) {
        dot += __shfl_down_sync(0xffffffffu, dot, off);
        kk  += __shfl_down_sync(0xffffffffu, kk,  off);
        tt  += __shfl_down_sync(0xffffffffu, tt,  off);
    }
    if (lane == 0) {
        float denom = fmaxf(sqrtf(tt) * sqrtf(kk), 1e-6f);
        s_cos[warp] = dot / denom;
    }
    __syncthreads();

    if (threadIdx.x == 0) {
        float mx = -1e30f;
        #pragma unroll
        for (int m = 0; m < M_SLOTS; m++) mx = fmaxf(mx, s_cos[m]);
        float e[M_SLOTS];
        float sum = 0.f;
        #pragma unroll
        for (int m = 0; m < M_SLOTS; m++) {
            e[m] = __expf(s_cos[m] - mx);
            sum += e[m];
        }
        float inv = 1.0f / sum;
        #pragma unroll
        for (int m = 0; m < M_SLOTS; m++) g_w[m] = e[m] * inv;
    }
}

// ---------------------------------------------------------------------------
// Kernel 2 (PDL secondary): streaming weighted sum.
// R15 body extended to 4 float4/thread: grid 1280 (V0 = exactly 256 tiles,
// no boundary straddle), 4 independent LDG.128 per slot iteration, same
// evict-first hints.
// ---------------------------------------------------------------------------
__global__ void __launch_bounds__(TPB) wsum_kernel(
        const float4* __restrict__ V0,
        const float4* __restrict__ V1,
        float4* __restrict__ out,
        int nv4_0, int nv4_1) {
    const int tid   = threadIdx.x;
    const int tile0 = blockIdx.x * TILE_F4;       // 1024 f4 per block, exact fit

    const float4* __restrict__ V;
    size_t stride;
    int base;
    if (tile0 < nv4_0) { V = V0; base = tile0;          stride = (size_t)nv4_0; }
    else               { V = V1; base = tile0 - nv4_0;  stride = (size_t)nv4_1; }

#if __CUDA_ARCH__ >= 900
    cudaGridDependencySynchronize();
#endif

    float w[M_SLOTS];
    #pragma unroll
    for (int m = 0; m < M_SLOTS; m++) w[m] = g_w[m];

    float4 acc0 = make_float4(0.f, 0.f, 0.f, 0.f);
    float4 acc1 = acc0, acc2 = acc0, acc3 = acc0;

    #pragma unroll
    for (int m = 0; m < M_SLOTS; m++) {
        const float4* p = V + (size_t)m * stride + (size_t)base + tid;
        float4 a, b, c, d;
        asm volatile("ld.global.cs.v4.f32 {%0, %1, %2, %3}, [%4];"
                     : "=f"(a.x), "=f"(a.y), "=f"(a.z), "=f"(a.w) : "l"(p));
        asm volatile("ld.global.cs.v4.f32 {%0, %1, %2, %3}, [%4];"
                     : "=f"(b.x), "=f"(b.y), "=f"(b.z), "=f"(b.w) : "l"(p + TPB));
        asm volatile("ld.global.cs.v4.f32 {%0, %1, %2, %3}, [%4];"
                     : "=f"(c.x), "=f"(c.y), "=f"(c.z), "=f"(c.w) : "l"(p + 2 * TPB));
        asm volatile("ld.global.cs.v4.f32 {%0, %1, %2, %3}, [%4];"
                     : "=f"(d.x), "=f"(d.y), "=f"(d.z), "=f"(d.w) : "l"(p + 3 * TPB));
        float wm = w[m];
        acc0.x = fmaf(wm, a.x, acc0.x); acc0.y = fmaf(wm, a.y, acc0.y);
        acc0.z = fmaf(wm, a.z, acc0.z); acc0.w = fmaf(wm, a.w, acc0.w);
        acc1.x = fmaf(wm, b.x, acc1.x); acc1.y = fmaf(wm, b.y, acc1.y);
        acc1.z = fmaf(wm, b.z, acc1.z); acc1.w = fmaf(wm, b.w, acc1.w);
        acc2.x = fmaf(wm, c.x, acc2.x); acc2.y = fmaf(wm, c.y, acc2.y);
        acc2.z = fmaf(wm, c.z, acc2.z); acc2.w = fmaf(wm, c.w, acc2.w);
        acc3.x = fmaf(wm, d.x, acc3.x); acc3.y = fmaf(wm, d.y, acc3.y);
        acc3.z = fmaf(wm, d.z, acc3.z); acc3.w = fmaf(wm, d.w, acc3.w);
    }

    float4* dst = out + tile0 + tid;
    asm volatile("st.global.cs.v4.f32 [%0], {%1, %2, %3, %4};"
                 :: "l"(dst), "f"(acc0.x), "f"(acc0.y), "f"(acc0.z), "f"(acc0.w)
                 : "memory");
    asm volatile("st.global.cs.v4.f32 [%0], {%1, %2, %3, %4};"
                 :: "l"(dst + TPB), "f"(acc1.x), "f"(acc1.y), "f"(acc1.z), "f"(acc1.w)
                 : "memory");
    asm volatile("st.global.cs.v4.f32 [%0], {%1, %2, %3, %4};"
                 :: "l"(dst + 2 * TPB), "f"(acc2.x), "f"(acc2.y), "f"(acc2.z), "f"(acc2.w)
                 : "memory");
    asm volatile("st.global.cs.v4.f32 [%0], {%1, %2, %3, %4};"
                 :: "l"(dst + 3 * TPB), "f"(acc3.x), "f"(acc3.y), "f"(acc3.z), "f"(acc3.w)
                 : "memory");
}

// ---------------------------------------------------------------------------
// Launch contract
// Inputs (metadata order): task_emb [1,1024] f32, K_memory [16,1024] f32,
//                          V0 [16,1024,1024] f32, V1 [16,1024,4096] f32
// Output: rec0 [1024,1024] f32 followed by rec1 [1024,4096] f32
// ---------------------------------------------------------------------------
extern "C" void kernel_launch(void* const* d_in, const int* in_sizes, int n_in,
                              void* d_out, int out_size) {
    const float* task_emb = (const float*)d_in[0];
    const float* K_memory = (const float*)d_in[1];
    const float* V0       = (const float*)d_in[2];
    const float* V1       = (const float*)d_in[3];
    float* out = (float*)d_out;

    const int n0 = in_sizes[2] / M_SLOTS;   // 1024*1024
    const int n1 = in_sizes[3] / M_SLOTS;   // 1024*4096
    const int nv4_0 = n0 / 4;               // 262144 (= 256 tiles of 1024 f4)
    const int nv4_1 = n1 / 4;               // 1048576
    const int total = nv4_0 + nv4_1;        // 1310720 = 1280 * 1024 exactly

    weights_kernel<<<1, 512>>>(task_emb, K_memory);

    // Secondary with programmatic stream serialization (reproducibly +0.5us).
    cudaLaunchConfig_t cfg = {};
    cfg.gridDim  = dim3((unsigned)(total / TILE_F4));     // 1280
    cfg.blockDim = dim3(TPB);
    cfg.dynamicSmemBytes = 0;
    cfg.stream = 0;

    cudaLaunchAttribute attrs[1];
    attrs[0].id = cudaLaunchAttributeProgrammaticStreamSerialization;
    attrs[0].val.programmaticStreamSerializationAllowed = 1;
    cfg.attrs = attrs;
    cfg.numAttrs = 1;

    cudaLaunchKernelEx(&cfg, wsum_kernel,
                       (const float4*)V0, (const float4*)V1,
                       (float4*)out, nv4_0, nv4_1);
}